// round 4
// baseline (speedup 1.0000x reference)
#include <cuda_runtime.h>
#include <cstdint>

// Problem constants
#define BATCH   2048
#define NTOK    64
#define DIM     512
#define NH      16
#define HD      32
#define MROWS   (BATCH * NTOK)      // 131072
#define QKVCOLS (3 * DIM)           // 1536
#define SCALE   0.17677669529663687f // 32^-0.5

// Scratch (allocation-free: __device__ globals)
__device__ float g_qkv[(size_t)MROWS * QKVCOLS];   // [B*N, 1536]
__device__ float g_attn[(size_t)MROWS * DIM];      // [B*N, 512] (tf32-rounded)
__device__ float g_xr[(size_t)MROWS * DIM];        // tf32-rounded x
__device__ float g_wqkv[(size_t)QKVCOLS * DIM];    // tf32-rounded W_qkv
__device__ float g_wproj[(size_t)DIM * DIM];       // tf32-rounded W_proj

__device__ __forceinline__ float tf32r(float x) {
    float y;
    asm("cvt.rna.tf32.f32 %0, %1;" : "=f"(y) : "f"(x));
    return y;
}

__device__ __forceinline__ uint32_t smem_u32(const void* p) {
    uint32_t a;
    asm("{ .reg .u64 t; cvta.to.shared.u64 t, %1; cvt.u32.u64 %0, t; }" : "=r"(a) : "l"(p));
    return a;
}

__device__ __forceinline__ void cp16(uint32_t s, const void* g) {
    asm volatile("cp.async.cg.shared.global [%0], [%1], 16;" :: "r"(s), "l"(g));
}

__device__ __forceinline__ void mma_tf32(float* d, const uint32_t* a, const uint32_t* b) {
    asm volatile(
        "mma.sync.aligned.m16n8k8.row.col.f32.tf32.tf32.f32 "
        "{%0,%1,%2,%3}, {%4,%5,%6,%7}, {%8,%9}, {%0,%1,%2,%3};"
        : "+f"(d[0]), "+f"(d[1]), "+f"(d[2]), "+f"(d[3])
        : "r"(a[0]), "r"(a[1]), "r"(a[2]), "r"(a[3]), "r"(b[0]), "r"(b[1]));
}

// ---------------------------------------------------------------------------
// Pre-round pass: out[i] = tf32_rna(in[i])  (float4)
// ---------------------------------------------------------------------------
__global__ void __launch_bounds__(256) round4(const float4* __restrict__ in,
                                              float4* __restrict__ out, int n4) {
    int i = blockIdx.x * blockDim.x + threadIdx.x;
    if (i < n4) {
        float4 v = in[i];
        v.x = tf32r(v.x); v.y = tf32r(v.y); v.z = tf32r(v.z); v.w = tf32r(v.w);
        out[i] = v;
    }
}

// ---------------------------------------------------------------------------
// GEMM: C[M,N] = A[M,K] @ W[N,K]^T + bias[N]   (A,W pre-rounded to tf32)
// Block tile 128x256, 256 threads = 8 warps (2x4), warp tile 64x64.
// cp.async 3-stage pipeline, ONE __syncthreads per k-tile.
// Padded rows (36 floats / 144B) -> conflict-free scalar fragment LDS.
// ---------------------------------------------------------------------------
#define BM 128
#define BN 256
#define BK 32
#define LDT 36
#define ROWB 144                          // bytes per smem row
#define A_BYTES (128 * ROWB)              // 18432
#define B_BYTES (256 * ROWB)              // 36864
#define STG (A_BYTES + B_BYTES)           // 55296 per stage
#define STAGES 3
#define GSMEM (STAGES * STG)              // 165888 B

__global__ void __launch_bounds__(256, 1) gemm_hmma(
    const float* __restrict__ A, const float* __restrict__ W,
    const float* __restrict__ bias, float* __restrict__ C,
    int N, int K)
{
    extern __shared__ float smem[];
    const uint32_t sb = smem_u32(smem);
    const int tid  = threadIdx.x;
    const int lane = tid & 31;
    const int warp = tid >> 5;
    const int wm   = warp >> 2;              // 0..1 (row of warp grid)
    const int wn   = warp & 3;               // 0..3 (col of warp grid)
    const int mb   = blockIdx.y * BM;
    const int nb   = blockIdx.x * BN;

    // cp.async mapping: 32 rows x 8 chunks(16B) per 256 threads; p adds 32 rows
    const int jr = tid >> 3;                 // row 0..31 (+32p)
    const int cb = tid & 7;                  // 16B chunk within row
    const float* Ag = A + (size_t)(mb + jr) * K + cb * 4;
    const float* Wg = W + (size_t)(nb + jr) * K + cb * 4;
    const uint32_t soff = (uint32_t)(jr * ROWB + cb * 16);

    // prologue: tiles 0,1 -> slots 0,1
    #pragma unroll
    for (int s = 0; s < 2; s++) {
        const uint32_t b = sb + s * STG;
        #pragma unroll
        for (int p = 0; p < 4; p++)
            cp16(b + soff + p * 32 * ROWB, Ag + s * BK + (size_t)p * 32 * K);
        #pragma unroll
        for (int p = 0; p < 8; p++)
            cp16(b + A_BYTES + soff + p * 32 * ROWB, Wg + s * BK + (size_t)p * 32 * K);
        asm volatile("cp.async.commit_group;" ::: "memory");
    }

    float acc[4][8][4] = {};
    const int KT = K / BK;

    for (int kt = 0; kt < KT; kt++) {
        asm volatile("cp.async.wait_group %0;" :: "n"(1) : "memory");
        __syncthreads();   // tile kt visible to all; slot (kt-1)%3 reads finished

        // prefetch tile kt+2 into slot (kt+2)%3 (== slot consumed at iter kt-1)
        const int nk = kt + 2;
        if (nk < KT) {
            const uint32_t b = sb + (nk % STAGES) * STG;
            #pragma unroll
            for (int p = 0; p < 4; p++)
                cp16(b + soff + p * 32 * ROWB, Ag + nk * BK + (size_t)p * 32 * K);
            #pragma unroll
            for (int p = 0; p < 8; p++)
                cp16(b + A_BYTES + soff + p * 32 * ROWB, Wg + nk * BK + (size_t)p * 32 * K);
            asm volatile("cp.async.commit_group;" ::: "memory");
        }

        const int buf = kt % STAGES;
        const float* Ab = smem + buf * (STG / 4) + (wm * 64) * LDT;
        const float* Bb = smem + buf * (STG / 4) + (A_BYTES / 4) + (wn * 64) * LDT;

        #pragma unroll
        for (int ks = 0; ks < 4; ks++) {
            const int k8 = ks * 8;
            uint32_t afr[4][4], bfr[8][2];
            #pragma unroll
            for (int mi = 0; mi < 4; mi++) {
                const float* p = Ab + (mi * 16 + (lane >> 2)) * LDT + k8 + (lane & 3);
                afr[mi][0] = __float_as_uint(p[0]);
                afr[mi][1] = __float_as_uint(p[8 * LDT]);
                afr[mi][2] = __float_as_uint(p[4]);
                afr[mi][3] = __float_as_uint(p[8 * LDT + 4]);
            }
            #pragma unroll
            for (int ni = 0; ni < 8; ni++) {
                const float* p = Bb + (ni * 8 + (lane >> 2)) * LDT + k8 + (lane & 3);
                bfr[ni][0] = __float_as_uint(p[0]);
                bfr[ni][1] = __float_as_uint(p[4]);
            }
            #pragma unroll
            for (int mi = 0; mi < 4; mi++)
                #pragma unroll
                for (int ni = 0; ni < 8; ni++)
                    mma_tf32(acc[mi][ni], afr[mi], bfr[ni]);
        }
    }

    // epilogue: +bias, fp32 stores
    #pragma unroll
    for (int mi = 0; mi < 4; mi++) {
        const int row = mb + wm * 64 + mi * 16 + (lane >> 2);
        #pragma unroll
        for (int ni = 0; ni < 8; ni++) {
            const int col = nb + wn * 64 + ni * 8 + (lane & 3) * 2;
            const float b0 = __ldg(bias + col), b1 = __ldg(bias + col + 1);
            float* Cp = C + (size_t)row * N + col;
            *(float2*)Cp = make_float2(acc[mi][ni][0] + b0, acc[mi][ni][1] + b1);
            *(float2*)(Cp + (size_t)8 * N) =
                make_float2(acc[mi][ni][2] + b0, acc[mi][ni][3] + b1);
        }
    }
}

// ---------------------------------------------------------------------------
// Attention: one (b, h) per block, 128 threads, mma.sync.
// Output stored tf32-rounded (feeds proj GEMM directly).
// ---------------------------------------------------------------------------
__global__ void __launch_bounds__(128) attn_kernel(
    const float* __restrict__ qkv, const float* __restrict__ btab,
    float* __restrict__ out)
{
    __shared__ float Qs[64][36];
    __shared__ float Ks[64][36];
    __shared__ float S[64][68];
    __shared__ float Vt[32][68];

    const int bh = blockIdx.x;
    const int b = bh >> 4;
    const int h = bh & 15;
    const int tid = threadIdx.x;
    const int lane = tid & 31;
    const int warp = tid >> 5;

    const float* base = qkv + (size_t)b * NTOK * QKVCOLS + h * HD;

    #pragma unroll
    for (int i = 0; i < 4; i++) {
        const int id = tid + i * 128;
        const int n = id >> 3;
        const int c4 = (id & 7) * 4;
        float4 q = *(const float4*)(base + (size_t)n * QKVCOLS + c4);
        q.x = tf32r(q.x * SCALE); q.y = tf32r(q.y * SCALE);
        q.z = tf32r(q.z * SCALE); q.w = tf32r(q.w * SCALE);
        *(float4*)(&Qs[n][c4]) = q;
        float4 k = *(const float4*)(base + (size_t)n * QKVCOLS + DIM + c4);
        k.x = tf32r(k.x); k.y = tf32r(k.y); k.z = tf32r(k.z); k.w = tf32r(k.w);
        *(float4*)(&Ks[n][c4]) = k;
    }
    for (int i = tid; i < NTOK * HD; i += 128) {
        const int m = i >> 5, d = i & 31;
        Vt[d][m] = tf32r(base[(size_t)m * QKVCOLS + 2 * DIM + d]);
    }
    __syncthreads();

    float sacc[8][4] = {};
    #pragma unroll
    for (int ks = 0; ks < 4; ks++) {
        const int k8 = ks * 8;
        uint32_t af[4];
        const float* p = &Qs[warp * 16 + (lane >> 2)][k8 + (lane & 3)];
        af[0] = __float_as_uint(p[0]);
        af[1] = __float_as_uint(p[8 * 36]);
        af[2] = __float_as_uint(p[4]);
        af[3] = __float_as_uint(p[8 * 36 + 4]);
        #pragma unroll
        for (int ni = 0; ni < 8; ni++) {
            uint32_t bf[2];
            const float* q = &Ks[ni * 8 + (lane >> 2)][k8 + (lane & 3)];
            bf[0] = __float_as_uint(q[0]);
            bf[1] = __float_as_uint(q[4]);
            mma_tf32(sacc[ni], af, bf);
        }
    }
    {
        const int rA = warp * 16 + (lane >> 2);
        #pragma unroll
        for (int ni = 0; ni < 8; ni++) {
            #pragma unroll
            for (int e = 0; e < 4; e++) {
                const int row = rA + ((e >= 2) ? 8 : 0);
                const int col = ni * 8 + (lane & 3) * 2 + (e & 1);
                const int yi = row >> 3, xi = row & 7;
                const int yj = col >> 3, xj = col & 7;
                const int idx = (yi - yj + 7) * 15 + (xi - xj + 7);
                S[row][col] = sacc[ni][e] + btab[idx * NH + h];
            }
        }
    }
    __syncthreads();

    {
        const int row = tid >> 1;
        const int half = (tid & 1) * 32;
        float mx = -1e30f;
        #pragma unroll
        for (int j = 0; j < 32; j++) mx = fmaxf(mx, S[row][half + j]);
        mx = fmaxf(mx, __shfl_xor_sync(0xffffffffu, mx, 1));
        float ev[32];
        float sum = 0.f;
        #pragma unroll
        for (int j = 0; j < 32; j++) { ev[j] = __expf(S[row][half + j] - mx); sum += ev[j]; }
        sum += __shfl_xor_sync(0xffffffffu, sum, 1);
        const float inv = 1.f / sum;
        #pragma unroll
        for (int j = 0; j < 32; j++) S[row][half + j] = tf32r(ev[j] * inv);
    }
    __syncthreads();

    float oacc[4][4] = {};
    #pragma unroll
    for (int ks = 0; ks < 8; ks++) {
        const int k8 = ks * 8;
        uint32_t af[4];
        const float* p = &S[warp * 16 + (lane >> 2)][k8 + (lane & 3)];
        af[0] = __float_as_uint(p[0]);
        af[1] = __float_as_uint(p[8 * 68]);
        af[2] = __float_as_uint(p[4]);
        af[3] = __float_as_uint(p[8 * 68 + 4]);
        #pragma unroll
        for (int ni = 0; ni < 4; ni++) {
            uint32_t bf[2];
            const float* q = &Vt[ni * 8 + (lane >> 2)][k8 + (lane & 3)];
            bf[0] = __float_as_uint(q[0]);
            bf[1] = __float_as_uint(q[4]);
            mma_tf32(oacc[ni], af, bf);
        }
    }
    {
        float* ob = out + (size_t)b * NTOK * DIM + h * HD;
        const int rA = warp * 16 + (lane >> 2);
        #pragma unroll
        for (int ni = 0; ni < 4; ni++) {
            const int col = ni * 8 + (lane & 3) * 2;
            *(float2*)(ob + (size_t)rA * DIM + col) =
                make_float2(tf32r(oacc[ni][0]), tf32r(oacc[ni][1]));
            *(float2*)(ob + (size_t)(rA + 8) * DIM + col) =
                make_float2(tf32r(oacc[ni][2]), tf32r(oacc[ni][3]));
        }
    }
}

// ---------------------------------------------------------------------------
extern "C" void kernel_launch(void* const* d_in, const int* in_sizes, int n_in,
                              void* d_out, int out_size)
{
    const float* x     = (const float*)d_in[0];
    const float* Wqkv  = (const float*)d_in[1];
    const float* bqkv  = (const float*)d_in[2];
    const float* Wproj = (const float*)d_in[3];
    const float* bproj = (const float*)d_in[4];
    const float* btab  = (const float*)d_in[5];
    float* out = (float*)d_out;

    float *qkvbuf, *attnbuf, *xr, *wqkvr, *wprojr;
    cudaGetSymbolAddress((void**)&qkvbuf, g_qkv);
    cudaGetSymbolAddress((void**)&attnbuf, g_attn);
    cudaGetSymbolAddress((void**)&xr, g_xr);
    cudaGetSymbolAddress((void**)&wqkvr, g_wqkv);
    cudaGetSymbolAddress((void**)&wprojr, g_wproj);

    cudaFuncSetAttribute(gemm_hmma, cudaFuncAttributeMaxDynamicSharedMemorySize, GSMEM);

    // 0) tf32-round inputs once
    {
        int n4 = MROWS * DIM / 4;
        round4<<<(n4 + 255) / 256, 256>>>((const float4*)x, (float4*)xr, n4);
        n4 = QKVCOLS * DIM / 4;
        round4<<<(n4 + 255) / 256, 256>>>((const float4*)Wqkv, (float4*)wqkvr, n4);
        n4 = DIM * DIM / 4;
        round4<<<(n4 + 255) / 256, 256>>>((const float4*)Wproj, (float4*)wprojr, n4);
    }

    // 1) QKV projection: [131072, 512] @ [1536, 512]^T + b_qkv
    gemm_hmma<<<dim3(QKVCOLS / BN, MROWS / BM), 256, GSMEM>>>(
        xr, wqkvr, bqkv, qkvbuf, QKVCOLS, DIM);

    // 2) Windowed attention per (b, h)
    attn_kernel<<<BATCH * NH, 128>>>(qkvbuf, btab, attnbuf);

    // 3) Output projection: [131072, 512] @ [512, 512]^T + b_proj
    gemm_hmma<<<dim3(DIM / BN, MROWS / BM), 256, GSMEM>>>(
        attnbuf, wprojr, bproj, out, DIM, DIM);
}

// round 5
// speedup vs baseline: 1.0279x; 1.0279x over previous
#include <cuda_runtime.h>
#include <cstdint>

// Problem constants
#define BATCH   2048
#define NTOK    64
#define DIM     512
#define NH      16
#define HD      32
#define MROWS   (BATCH * NTOK)      // 131072
#define QKVCOLS (3 * DIM)           // 1536
#define SCALE   0.17677669529663687f // 32^-0.5

// Scratch (allocation-free: __device__ globals)
__device__ float g_qkv[(size_t)MROWS * QKVCOLS];   // [B*N, 1536]
__device__ float g_attn[(size_t)MROWS * DIM];      // [B*N, 512] (tf32-rounded)
__device__ float g_xr[(size_t)MROWS * DIM];        // tf32-rounded x
__device__ float g_wqkv[(size_t)QKVCOLS * DIM];    // tf32-rounded W_qkv
__device__ float g_wproj[(size_t)DIM * DIM];       // tf32-rounded W_proj

__device__ __forceinline__ float tf32r(float x) {
    float y;
    asm("cvt.rna.tf32.f32 %0, %1;" : "=f"(y) : "f"(x));
    return y;
}

__device__ __forceinline__ uint32_t smem_u32(const void* p) {
    uint32_t a;
    asm("{ .reg .u64 t; cvta.to.shared.u64 t, %1; cvt.u32.u64 %0, t; }" : "=r"(a) : "l"(p));
    return a;
}

__device__ __forceinline__ void cp16(uint32_t s, const void* g) {
    asm volatile("cp.async.cg.shared.global [%0], [%1], 16;" :: "r"(s), "l"(g));
}

__device__ __forceinline__ void mma_tf32(float* d, const uint32_t* a, const uint32_t* b) {
    asm volatile(
        "mma.sync.aligned.m16n8k8.row.col.f32.tf32.tf32.f32 "
        "{%0,%1,%2,%3}, {%4,%5,%6,%7}, {%8,%9}, {%0,%1,%2,%3};"
        : "+f"(d[0]), "+f"(d[1]), "+f"(d[2]), "+f"(d[3])
        : "r"(a[0]), "r"(a[1]), "r"(a[2]), "r"(a[3]), "r"(b[0]), "r"(b[1]));
}

// ---------------------------------------------------------------------------
// Pre-round pass: out[i] = tf32_rna(in[i])  (float4)
// ---------------------------------------------------------------------------
__global__ void __launch_bounds__(256) round4(const float4* __restrict__ in,
                                              float4* __restrict__ out, int n4) {
    int i = blockIdx.x * blockDim.x + threadIdx.x;
    if (i < n4) {
        float4 v = in[i];
        v.x = tf32r(v.x); v.y = tf32r(v.y); v.z = tf32r(v.z); v.w = tf32r(v.w);
        out[i] = v;
    }
}

// ---------------------------------------------------------------------------
// GEMM: C[M,N] = A[M,K] @ W[N,K]^T + bias[N]   (A,W pre-rounded to tf32)
// 128x128x32 tiles, 256 threads (8 warps, 2x4), warp tile 64x32.
// 3-stage cp.async pipeline, ONE __syncthreads per k-tile, prefetch dist 2.
// 2 CTAs/SM (regs pinned to 128 by launch_bounds, smem 110592B).
// ---------------------------------------------------------------------------
#define BM 128
#define BN 128
#define BK 32
#define LDT 36
#define ROWB 144                         // bytes per smem row
#define STG_A (128 * ROWB)               // 18432 B
#define STG (2 * STG_A)                  // 36864 B per stage (A then B)
#define STAGES 3
#define GSMEM (STAGES * STG)             // 110592 B

__global__ void __launch_bounds__(256, 2) gemm_hmma(
    const float* __restrict__ A, const float* __restrict__ W,
    const float* __restrict__ bias, float* __restrict__ C,
    int N, int K)
{
    extern __shared__ float smem[];
    const uint32_t sb = smem_u32(smem);
    const int tid  = threadIdx.x;
    const int lane = tid & 31;
    const int warp = tid >> 5;
    const int wm   = warp >> 2;              // 0..1
    const int wn   = warp & 3;               // 0..3
    const int mb   = blockIdx.y * BM;
    const int nb   = blockIdx.x * BN;

    // cp.async mapping: 32 rows x 8 chunks(16B); p adds 32 rows
    const int jr = tid >> 3;
    const int cb = tid & 7;
    const float* Ag = A + (size_t)(mb + jr) * K + cb * 4;
    const float* Wg = W + (size_t)(nb + jr) * K + cb * 4;
    const uint32_t soff = (uint32_t)(jr * ROWB + cb * 16);

    // prologue: tiles 0,1 -> slots 0,1
    #pragma unroll
    for (int s = 0; s < 2; s++) {
        const uint32_t b = sb + s * STG;
        #pragma unroll
        for (int p = 0; p < 4; p++)
            cp16(b + soff + p * 32 * ROWB, Ag + s * BK + (size_t)p * 32 * K);
        #pragma unroll
        for (int p = 0; p < 4; p++)
            cp16(b + STG_A + soff + p * 32 * ROWB, Wg + s * BK + (size_t)p * 32 * K);
        asm volatile("cp.async.commit_group;" ::: "memory");
    }

    float acc[4][4][4] = {};
    const int KT = K / BK;

    for (int kt = 0; kt < KT; kt++) {
        asm volatile("cp.async.wait_group %0;" :: "n"(1) : "memory");
        __syncthreads();   // tile kt visible; slot (kt+2)%3's old reads done

        const int nk = kt + 2;
        if (nk < KT) {
            const uint32_t b = sb + (nk % STAGES) * STG;
            #pragma unroll
            for (int p = 0; p < 4; p++)
                cp16(b + soff + p * 32 * ROWB, Ag + nk * BK + (size_t)p * 32 * K);
            #pragma unroll
            for (int p = 0; p < 4; p++)
                cp16(b + STG_A + soff + p * 32 * ROWB, Wg + nk * BK + (size_t)p * 32 * K);
            asm volatile("cp.async.commit_group;" ::: "memory");
        }

        const int buf = kt % STAGES;
        const float* Ab = smem + buf * (STG / 4) + (wm * 64) * LDT;
        const float* Bb = smem + buf * (STG / 4) + (STG_A / 4) + (wn * 32) * LDT;

        #pragma unroll
        for (int ks = 0; ks < 4; ks++) {
            const int k8 = ks * 8;
            uint32_t afr[4][4], bfr[4][2];
            #pragma unroll
            for (int mi = 0; mi < 4; mi++) {
                const float* p = Ab + (mi * 16 + (lane >> 2)) * LDT + k8 + (lane & 3);
                afr[mi][0] = __float_as_uint(p[0]);
                afr[mi][1] = __float_as_uint(p[8 * LDT]);
                afr[mi][2] = __float_as_uint(p[4]);
                afr[mi][3] = __float_as_uint(p[8 * LDT + 4]);
            }
            #pragma unroll
            for (int ni = 0; ni < 4; ni++) {
                const float* p = Bb + (ni * 8 + (lane >> 2)) * LDT + k8 + (lane & 3);
                bfr[ni][0] = __float_as_uint(p[0]);
                bfr[ni][1] = __float_as_uint(p[4]);
            }
            #pragma unroll
            for (int mi = 0; mi < 4; mi++)
                #pragma unroll
                for (int ni = 0; ni < 4; ni++)
                    mma_tf32(acc[mi][ni], afr[mi], bfr[ni]);
        }
    }

    // epilogue: +bias, fp32 stores
    #pragma unroll
    for (int mi = 0; mi < 4; mi++) {
        const int row = mb + wm * 64 + mi * 16 + (lane >> 2);
        #pragma unroll
        for (int ni = 0; ni < 4; ni++) {
            const int col = nb + wn * 32 + ni * 8 + (lane & 3) * 2;
            const float b0 = __ldg(bias + col), b1 = __ldg(bias + col + 1);
            float* Cp = C + (size_t)row * N + col;
            *(float2*)Cp = make_float2(acc[mi][ni][0] + b0, acc[mi][ni][1] + b1);
            *(float2*)(Cp + (size_t)8 * N) =
                make_float2(acc[mi][ni][2] + b0, acc[mi][ni][3] + b1);
        }
    }
}

// ---------------------------------------------------------------------------
// Attention: one (b, h) per block, 128 threads, mma.sync.
// Output stored tf32-rounded (feeds proj GEMM directly).
// ---------------------------------------------------------------------------
__global__ void __launch_bounds__(128) attn_kernel(
    const float* __restrict__ qkv, const float* __restrict__ btab,
    float* __restrict__ out)
{
    __shared__ float Qs[64][36];
    __shared__ float Ks[64][36];
    __shared__ float S[64][68];
    __shared__ float Vt[32][68];

    const int bh = blockIdx.x;
    const int b = bh >> 4;
    const int h = bh & 15;
    const int tid = threadIdx.x;
    const int lane = tid & 31;
    const int warp = tid >> 5;

    const float* base = qkv + (size_t)b * NTOK * QKVCOLS + h * HD;

    #pragma unroll
    for (int i = 0; i < 4; i++) {
        const int id = tid + i * 128;
        const int n = id >> 3;
        const int c4 = (id & 7) * 4;
        float4 q = *(const float4*)(base + (size_t)n * QKVCOLS + c4);
        q.x = tf32r(q.x * SCALE); q.y = tf32r(q.y * SCALE);
        q.z = tf32r(q.z * SCALE); q.w = tf32r(q.w * SCALE);
        *(float4*)(&Qs[n][c4]) = q;
        float4 k = *(const float4*)(base + (size_t)n * QKVCOLS + DIM + c4);
        k.x = tf32r(k.x); k.y = tf32r(k.y); k.z = tf32r(k.z); k.w = tf32r(k.w);
        *(float4*)(&Ks[n][c4]) = k;
    }
    for (int i = tid; i < NTOK * HD; i += 128) {
        const int m = i >> 5, d = i & 31;
        Vt[d][m] = tf32r(base[(size_t)m * QKVCOLS + 2 * DIM + d]);
    }
    __syncthreads();

    float sacc[8][4] = {};
    #pragma unroll
    for (int ks = 0; ks < 4; ks++) {
        const int k8 = ks * 8;
        uint32_t af[4];
        const float* p = &Qs[warp * 16 + (lane >> 2)][k8 + (lane & 3)];
        af[0] = __float_as_uint(p[0]);
        af[1] = __float_as_uint(p[8 * 36]);
        af[2] = __float_as_uint(p[4]);
        af[3] = __float_as_uint(p[8 * 36 + 4]);
        #pragma unroll
        for (int ni = 0; ni < 8; ni++) {
            uint32_t bf[2];
            const float* q = &Ks[ni * 8 + (lane >> 2)][k8 + (lane & 3)];
            bf[0] = __float_as_uint(q[0]);
            bf[1] = __float_as_uint(q[4]);
            mma_tf32(sacc[ni], af, bf);
        }
    }
    {
        const int rA = warp * 16 + (lane >> 2);
        #pragma unroll
        for (int ni = 0; ni < 8; ni++) {
            #pragma unroll
            for (int e = 0; e < 4; e++) {
                const int row = rA + ((e >= 2) ? 8 : 0);
                const int col = ni * 8 + (lane & 3) * 2 + (e & 1);
                const int yi = row >> 3, xi = row & 7;
                const int yj = col >> 3, xj = col & 7;
                const int idx = (yi - yj + 7) * 15 + (xi - xj + 7);
                S[row][col] = sacc[ni][e] + btab[idx * NH + h];
            }
        }
    }
    __syncthreads();

    {
        const int row = tid >> 1;
        const int half = (tid & 1) * 32;
        float mx = -1e30f;
        #pragma unroll
        for (int j = 0; j < 32; j++) mx = fmaxf(mx, S[row][half + j]);
        mx = fmaxf(mx, __shfl_xor_sync(0xffffffffu, mx, 1));
        float ev[32];
        float sum = 0.f;
        #pragma unroll
        for (int j = 0; j < 32; j++) { ev[j] = __expf(S[row][half + j] - mx); sum += ev[j]; }
        sum += __shfl_xor_sync(0xffffffffu, sum, 1);
        const float inv = 1.f / sum;
        #pragma unroll
        for (int j = 0; j < 32; j++) S[row][half + j] = tf32r(ev[j] * inv);
    }
    __syncthreads();

    float oacc[4][4] = {};
    #pragma unroll
    for (int ks = 0; ks < 8; ks++) {
        const int k8 = ks * 8;
        uint32_t af[4];
        const float* p = &S[warp * 16 + (lane >> 2)][k8 + (lane & 3)];
        af[0] = __float_as_uint(p[0]);
        af[1] = __float_as_uint(p[8 * 68]);
        af[2] = __float_as_uint(p[4]);
        af[3] = __float_as_uint(p[8 * 68 + 4]);
        #pragma unroll
        for (int ni = 0; ni < 4; ni++) {
            uint32_t bf[2];
            const float* q = &Vt[ni * 8 + (lane >> 2)][k8 + (lane & 3)];
            bf[0] = __float_as_uint(q[0]);
            bf[1] = __float_as_uint(q[4]);
            mma_tf32(oacc[ni], af, bf);
        }
    }
    {
        float* ob = out + (size_t)b * NTOK * DIM + h * HD;
        const int rA = warp * 16 + (lane >> 2);
        #pragma unroll
        for (int ni = 0; ni < 4; ni++) {
            const int col = ni * 8 + (lane & 3) * 2;
            *(float2*)(ob + (size_t)rA * DIM + col) =
                make_float2(tf32r(oacc[ni][0]), tf32r(oacc[ni][1]));
            *(float2*)(ob + (size_t)(rA + 8) * DIM + col) =
                make_float2(tf32r(oacc[ni][2]), tf32r(oacc[ni][3]));
        }
    }
}

// ---------------------------------------------------------------------------
extern "C" void kernel_launch(void* const* d_in, const int* in_sizes, int n_in,
                              void* d_out, int out_size)
{
    const float* x     = (const float*)d_in[0];
    const float* Wqkv  = (const float*)d_in[1];
    const float* bqkv  = (const float*)d_in[2];
    const float* Wproj = (const float*)d_in[3];
    const float* bproj = (const float*)d_in[4];
    const float* btab  = (const float*)d_in[5];
    float* out = (float*)d_out;

    float *qkvbuf, *attnbuf, *xr, *wqkvr, *wprojr;
    cudaGetSymbolAddress((void**)&qkvbuf, g_qkv);
    cudaGetSymbolAddress((void**)&attnbuf, g_attn);
    cudaGetSymbolAddress((void**)&xr, g_xr);
    cudaGetSymbolAddress((void**)&wqkvr, g_wqkv);
    cudaGetSymbolAddress((void**)&wprojr, g_wproj);

    cudaFuncSetAttribute(gemm_hmma, cudaFuncAttributeMaxDynamicSharedMemorySize, GSMEM);

    // 0) tf32-round inputs once
    {
        int n4 = MROWS * DIM / 4;
        round4<<<(n4 + 255) / 256, 256>>>((const float4*)x, (float4*)xr, n4);
        n4 = QKVCOLS * DIM / 4;
        round4<<<(n4 + 255) / 256, 256>>>((const float4*)Wqkv, (float4*)wqkvr, n4);
        n4 = DIM * DIM / 4;
        round4<<<(n4 + 255) / 256, 256>>>((const float4*)Wproj, (float4*)wprojr, n4);
    }

    // 1) QKV projection: [131072, 512] @ [1536, 512]^T + b_qkv
    gemm_hmma<<<dim3(QKVCOLS / BN, MROWS / BM), 256, GSMEM>>>(
        xr, wqkvr, bqkv, qkvbuf, QKVCOLS, DIM);

    // 2) Windowed attention per (b, h)
    attn_kernel<<<BATCH * NH, 128>>>(qkvbuf, btab, attnbuf);

    // 3) Output projection: [131072, 512] @ [512, 512]^T + b_proj
    gemm_hmma<<<dim3(DIM / BN, MROWS / BM), 256, GSMEM>>>(
        attnbuf, wprojr, bproj, out, DIM, DIM);
}

// round 6
// speedup vs baseline: 1.0307x; 1.0027x over previous
#include <cuda_runtime.h>
#include <cstdint>

// Problem constants
#define BATCH   2048
#define NTOK    64
#define DIM     512
#define NH      16
#define HD      32
#define MROWS   (BATCH * NTOK)      // 131072
#define QKVCOLS (3 * DIM)           // 1536
#define SCALE   0.17677669529663687f // 32^-0.5

// Scratch (allocation-free: __device__ globals)
__device__ float g_qkv[(size_t)MROWS * QKVCOLS];   // [B*N, 1536]
__device__ float g_attn[(size_t)MROWS * DIM];      // [B*N, 512] (tf32-rounded)
__device__ float g_wqkv[(size_t)QKVCOLS * DIM];    // tf32-rounded W_qkv
__device__ float g_wproj[(size_t)DIM * DIM];       // tf32-rounded W_proj

__device__ __forceinline__ float tf32r(float x) {
    float y;
    asm("cvt.rna.tf32.f32 %0, %1;" : "=f"(y) : "f"(x));
    return y;
}
__device__ __forceinline__ uint32_t tf32ru(uint32_t x) {
    float y;
    asm("cvt.rna.tf32.f32 %0, %1;" : "=f"(y) : "f"(__uint_as_float(x)));
    return __float_as_uint(y);
}

__device__ __forceinline__ uint32_t smem_u32(const void* p) {
    uint32_t a;
    asm("{ .reg .u64 t; cvta.to.shared.u64 t, %1; cvt.u32.u64 %0, t; }" : "=r"(a) : "l"(p));
    return a;
}

__device__ __forceinline__ void cp16(uint32_t s, const void* g) {
    asm volatile("cp.async.cg.shared.global [%0], [%1], 16;" :: "r"(s), "l"(g));
}

__device__ __forceinline__ void mma_tf32(float* d, const uint32_t* a, const uint32_t* b) {
    asm volatile(
        "mma.sync.aligned.m16n8k8.row.col.f32.tf32.tf32.f32 "
        "{%0,%1,%2,%3}, {%4,%5,%6,%7}, {%8,%9}, {%0,%1,%2,%3};"
        : "+f"(d[0]), "+f"(d[1]), "+f"(d[2]), "+f"(d[3])
        : "r"(a[0]), "r"(a[1]), "r"(a[2]), "r"(a[3]), "r"(b[0]), "r"(b[1]));
}

// ---------------------------------------------------------------------------
// Pre-round pass for weights only: out[i] = tf32_rna(in[i])
// ---------------------------------------------------------------------------
__global__ void __launch_bounds__(256) round4(const float4* __restrict__ in,
                                              float4* __restrict__ out, int n4) {
    int i = blockIdx.x * blockDim.x + threadIdx.x;
    if (i < n4) {
        float4 v = in[i];
        v.x = tf32r(v.x); v.y = tf32r(v.y); v.z = tf32r(v.z); v.w = tf32r(v.w);
        out[i] = v;
    }
}

// ---------------------------------------------------------------------------
// GEMM: C[M,N] = A[M,K] @ W[N,K]^T + bias[N]
// 128x128x32 CTA tile, 128 threads = 4 warps (2x2), warp tile 64x64.
// 2-stage cp.async pipeline, 3 CTAs/SM. W pre-rounded; A optionally rounded
// in the fragment path (RND_A, for raw x input).
// ---------------------------------------------------------------------------
#define BM 128
#define BN 128
#define BK 32
#define LDT 36
#define ROWB 144                         // bytes per smem row
#define STG_A (128 * ROWB)               // 18432 B
#define STG (2 * STG_A)                  // 36864 B per stage (A then B)
#define GSMEM (2 * STG)                  // 73728 B

template<bool RND_A>
__global__ void __launch_bounds__(128, 3) gemm_hmma(
    const float* __restrict__ A, const float* __restrict__ W,
    const float* __restrict__ bias, float* __restrict__ C,
    int N, int K)
{
    extern __shared__ float smem[];
    const uint32_t sb = smem_u32(smem);
    const int tid  = threadIdx.x;
    const int lane = tid & 31;
    const int warp = tid >> 5;
    const int wm   = warp >> 1;              // 0..1
    const int wn   = warp & 1;               // 0..1
    const int mb   = blockIdx.y * BM;
    const int nb   = blockIdx.x * BN;

    // cp.async mapping: 16 rows x 8 chunks(16B) per 128 threads; p adds 16 rows
    const int jr = tid >> 3;                 // 0..15
    const int cb = tid & 7;
    const float* Ag = A + (size_t)(mb + jr) * K + cb * 4;
    const float* Wg = W + (size_t)(nb + jr) * K + cb * 4;
    const uint32_t soff = (uint32_t)(jr * ROWB + cb * 16);

    // prologue: tile 0 -> slot 0
    #pragma unroll
    for (int p = 0; p < 8; p++)
        cp16(sb + soff + p * 16 * ROWB, Ag + (size_t)p * 16 * K);
    #pragma unroll
    for (int p = 0; p < 8; p++)
        cp16(sb + STG_A + soff + p * 16 * ROWB, Wg + (size_t)p * 16 * K);
    asm volatile("cp.async.commit_group;" ::: "memory");

    float acc[4][8][4] = {};
    const int KT = K / BK;

    for (int kt = 0; kt < KT; kt++) {
        asm volatile("cp.async.wait_group 0;" ::: "memory");
        __syncthreads();   // tile kt visible to all; all warps done with kt-1

        const int nk = kt + 1;
        if (nk < KT) {
            const uint32_t b = sb + (nk & 1) * STG;
            #pragma unroll
            for (int p = 0; p < 8; p++)
                cp16(b + soff + p * 16 * ROWB, Ag + nk * BK + (size_t)p * 16 * K);
            #pragma unroll
            for (int p = 0; p < 8; p++)
                cp16(b + STG_A + soff + p * 16 * ROWB, Wg + nk * BK + (size_t)p * 16 * K);
            asm volatile("cp.async.commit_group;" ::: "memory");
        }

        const int buf = kt & 1;
        const float* Ab = smem + buf * (STG / 4) + (wm * 64) * LDT;
        const float* Bb = smem + buf * (STG / 4) + (STG_A / 4) + (wn * 64) * LDT;

        #pragma unroll
        for (int ks = 0; ks < 4; ks++) {
            const int k8 = ks * 8;
            uint32_t afr[4][4], bfr[8][2];
            #pragma unroll
            for (int mi = 0; mi < 4; mi++) {
                const float* p = Ab + (mi * 16 + (lane >> 2)) * LDT + k8 + (lane & 3);
                afr[mi][0] = __float_as_uint(p[0]);
                afr[mi][1] = __float_as_uint(p[8 * LDT]);
                afr[mi][2] = __float_as_uint(p[4]);
                afr[mi][3] = __float_as_uint(p[8 * LDT + 4]);
                if (RND_A) {
                    afr[mi][0] = tf32ru(afr[mi][0]);
                    afr[mi][1] = tf32ru(afr[mi][1]);
                    afr[mi][2] = tf32ru(afr[mi][2]);
                    afr[mi][3] = tf32ru(afr[mi][3]);
                }
            }
            #pragma unroll
            for (int ni = 0; ni < 8; ni++) {
                const float* p = Bb + (ni * 8 + (lane >> 2)) * LDT + k8 + (lane & 3);
                bfr[ni][0] = __float_as_uint(p[0]);
                bfr[ni][1] = __float_as_uint(p[4]);
            }
            #pragma unroll
            for (int mi = 0; mi < 4; mi++)
                #pragma unroll
                for (int ni = 0; ni < 8; ni++)
                    mma_tf32(acc[mi][ni], afr[mi], bfr[ni]);
        }
    }

    // epilogue: +bias, fp32 stores
    #pragma unroll
    for (int mi = 0; mi < 4; mi++) {
        const int row = mb + wm * 64 + mi * 16 + (lane >> 2);
        #pragma unroll
        for (int ni = 0; ni < 8; ni++) {
            const int col = nb + wn * 64 + ni * 8 + (lane & 3) * 2;
            const float b0 = __ldg(bias + col), b1 = __ldg(bias + col + 1);
            float* Cp = C + (size_t)row * N + col;
            *(float2*)Cp = make_float2(acc[mi][ni][0] + b0, acc[mi][ni][1] + b1);
            *(float2*)(Cp + (size_t)8 * N) =
                make_float2(acc[mi][ni][2] + b0, acc[mi][ni][3] + b1);
        }
    }
}

// ---------------------------------------------------------------------------
// Attention: one (b, h) per block, 128 threads, mma.sync.
// Output stored tf32-rounded (feeds proj GEMM directly).
// ---------------------------------------------------------------------------
__global__ void __launch_bounds__(128) attn_kernel(
    const float* __restrict__ qkv, const float* __restrict__ btab,
    float* __restrict__ out)
{
    __shared__ float Qs[64][36];
    __shared__ float Ks[64][36];
    __shared__ float S[64][68];
    __shared__ float Vt[32][68];

    const int bh = blockIdx.x;
    const int b = bh >> 4;
    const int h = bh & 15;
    const int tid = threadIdx.x;
    const int lane = tid & 31;
    const int warp = tid >> 5;

    const float* base = qkv + (size_t)b * NTOK * QKVCOLS + h * HD;

    #pragma unroll
    for (int i = 0; i < 4; i++) {
        const int id = tid + i * 128;
        const int n = id >> 3;
        const int c4 = (id & 7) * 4;
        float4 q = *(const float4*)(base + (size_t)n * QKVCOLS + c4);
        q.x = tf32r(q.x * SCALE); q.y = tf32r(q.y * SCALE);
        q.z = tf32r(q.z * SCALE); q.w = tf32r(q.w * SCALE);
        *(float4*)(&Qs[n][c4]) = q;
        float4 k = *(const float4*)(base + (size_t)n * QKVCOLS + DIM + c4);
        k.x = tf32r(k.x); k.y = tf32r(k.y); k.z = tf32r(k.z); k.w = tf32r(k.w);
        *(float4*)(&Ks[n][c4]) = k;
    }
    for (int i = tid; i < NTOK * HD; i += 128) {
        const int m = i >> 5, d = i & 31;
        Vt[d][m] = tf32r(base[(size_t)m * QKVCOLS + 2 * DIM + d]);
    }
    __syncthreads();

    float sacc[8][4] = {};
    #pragma unroll
    for (int ks = 0; ks < 4; ks++) {
        const int k8 = ks * 8;
        uint32_t af[4];
        const float* p = &Qs[warp * 16 + (lane >> 2)][k8 + (lane & 3)];
        af[0] = __float_as_uint(p[0]);
        af[1] = __float_as_uint(p[8 * 36]);
        af[2] = __float_as_uint(p[4]);
        af[3] = __float_as_uint(p[8 * 36 + 4]);
        #pragma unroll
        for (int ni = 0; ni < 8; ni++) {
            uint32_t bf[2];
            const float* q = &Ks[ni * 8 + (lane >> 2)][k8 + (lane & 3)];
            bf[0] = __float_as_uint(q[0]);
            bf[1] = __float_as_uint(q[4]);
            mma_tf32(sacc[ni], af, bf);
        }
    }
    {
        const int rA = warp * 16 + (lane >> 2);
        #pragma unroll
        for (int ni = 0; ni < 8; ni++) {
            #pragma unroll
            for (int e = 0; e < 4; e++) {
                const int row = rA + ((e >= 2) ? 8 : 0);
                const int col = ni * 8 + (lane & 3) * 2 + (e & 1);
                const int yi = row >> 3, xi = row & 7;
                const int yj = col >> 3, xj = col & 7;
                const int idx = (yi - yj + 7) * 15 + (xi - xj + 7);
                S[row][col] = sacc[ni][e] + btab[idx * NH + h];
            }
        }
    }
    __syncthreads();

    {
        const int row = tid >> 1;
        const int half = (tid & 1) * 32;
        float mx = -1e30f;
        #pragma unroll
        for (int j = 0; j < 32; j++) mx = fmaxf(mx, S[row][half + j]);
        mx = fmaxf(mx, __shfl_xor_sync(0xffffffffu, mx, 1));
        float ev[32];
        float sum = 0.f;
        #pragma unroll
        for (int j = 0; j < 32; j++) { ev[j] = __expf(S[row][half + j] - mx); sum += ev[j]; }
        sum += __shfl_xor_sync(0xffffffffu, sum, 1);
        const float inv = 1.f / sum;
        #pragma unroll
        for (int j = 0; j < 32; j++) S[row][half + j] = tf32r(ev[j] * inv);
    }
    __syncthreads();

    float oacc[4][4] = {};
    #pragma unroll
    for (int ks = 0; ks < 8; ks++) {
        const int k8 = ks * 8;
        uint32_t af[4];
        const float* p = &S[warp * 16 + (lane >> 2)][k8 + (lane & 3)];
        af[0] = __float_as_uint(p[0]);
        af[1] = __float_as_uint(p[8 * 68]);
        af[2] = __float_as_uint(p[4]);
        af[3] = __float_as_uint(p[8 * 68 + 4]);
        #pragma unroll
        for (int ni = 0; ni < 4; ni++) {
            uint32_t bf[2];
            const float* q = &Vt[ni * 8 + (lane >> 2)][k8 + (lane & 3)];
            bf[0] = __float_as_uint(q[0]);
            bf[1] = __float_as_uint(q[4]);
            mma_tf32(oacc[ni], af, bf);
        }
    }
    {
        float* ob = out + (size_t)b * NTOK * DIM + h * HD;
        const int rA = warp * 16 + (lane >> 2);
        #pragma unroll
        for (int ni = 0; ni < 4; ni++) {
            const int col = ni * 8 + (lane & 3) * 2;
            *(float2*)(ob + (size_t)rA * DIM + col) =
                make_float2(tf32r(oacc[ni][0]), tf32r(oacc[ni][1]));
            *(float2*)(ob + (size_t)(rA + 8) * DIM + col) =
                make_float2(tf32r(oacc[ni][2]), tf32r(oacc[ni][3]));
        }
    }
}

// ---------------------------------------------------------------------------
extern "C" void kernel_launch(void* const* d_in, const int* in_sizes, int n_in,
                              void* d_out, int out_size)
{
    const float* x     = (const float*)d_in[0];
    const float* Wqkv  = (const float*)d_in[1];
    const float* bqkv  = (const float*)d_in[2];
    const float* Wproj = (const float*)d_in[3];
    const float* bproj = (const float*)d_in[4];
    const float* btab  = (const float*)d_in[5];
    float* out = (float*)d_out;

    float *qkvbuf, *attnbuf, *wqkvr, *wprojr;
    cudaGetSymbolAddress((void**)&qkvbuf, g_qkv);
    cudaGetSymbolAddress((void**)&attnbuf, g_attn);
    cudaGetSymbolAddress((void**)&wqkvr, g_wqkv);
    cudaGetSymbolAddress((void**)&wprojr, g_wproj);

    cudaFuncSetAttribute(gemm_hmma<true>, cudaFuncAttributeMaxDynamicSharedMemorySize, GSMEM);
    cudaFuncSetAttribute(gemm_hmma<false>, cudaFuncAttributeMaxDynamicSharedMemorySize, GSMEM);

    // 0) tf32-round weights once (x handled in-GEMM)
    {
        int n4 = QKVCOLS * DIM / 4;
        round4<<<(n4 + 255) / 256, 256>>>((const float4*)Wqkv, (float4*)wqkvr, n4);
        n4 = DIM * DIM / 4;
        round4<<<(n4 + 255) / 256, 256>>>((const float4*)Wproj, (float4*)wprojr, n4);
    }

    // 1) QKV projection: [131072, 512] @ [1536, 512]^T + b_qkv (x rounded in-kernel)
    gemm_hmma<true><<<dim3(QKVCOLS / BN, MROWS / BM), 128, GSMEM>>>(
        x, wqkvr, bqkv, qkvbuf, QKVCOLS, DIM);

    // 2) Windowed attention per (b, h)
    attn_kernel<<<BATCH * NH, 128>>>(qkvbuf, btab, attnbuf);

    // 3) Output projection: [131072, 512] @ [512, 512]^T + b_proj
    gemm_hmma<false><<<dim3(DIM / BN, MROWS / BM), 128, GSMEM>>>(
        attnbuf, wprojr, bproj, out, DIM, DIM);
}

// round 7
// speedup vs baseline: 1.1083x; 1.0753x over previous
#include <cuda_runtime.h>
#include <cstdint>

// Problem constants
#define BATCH   2048
#define NTOK    64
#define DIM     512
#define NH      16
#define HD      32
#define MROWS   (BATCH * NTOK)      // 131072
#define QKVCOLS (3 * DIM)           // 1536
#define SCALE   0.17677669529663687f // 32^-0.5

// Scratch (allocation-free: __device__ globals)
__device__ float g_qkv[(size_t)MROWS * QKVCOLS];   // [B*N, 1536]
__device__ float g_attn[(size_t)MROWS * DIM];      // [B*N, 512] (tf32-rounded)
__device__ float g_xr[(size_t)MROWS * DIM];        // tf32-rounded x
__device__ float g_wqkv[(size_t)QKVCOLS * DIM];    // tf32-rounded W_qkv
__device__ float g_wproj[(size_t)DIM * DIM];       // tf32-rounded W_proj
__device__ float g_bias[NH * NTOK * NTOK];         // expanded rel-pos bias

__device__ __forceinline__ float tf32r(float x) {
    float y;
    asm("cvt.rna.tf32.f32 %0, %1;" : "=f"(y) : "f"(x));
    return y;
}

__device__ __forceinline__ uint32_t smem_u32(const void* p) {
    uint32_t a;
    asm("{ .reg .u64 t; cvta.to.shared.u64 t, %1; cvt.u32.u64 %0, t; }" : "=r"(a) : "l"(p));
    return a;
}

__device__ __forceinline__ void cp16(uint32_t s, const void* g) {
    asm volatile("cp.async.cg.shared.global [%0], [%1], 16;" :: "r"(s), "l"(g));
}

__device__ __forceinline__ void mma_tf32(float* d, const uint32_t* a, const uint32_t* b) {
    asm volatile(
        "mma.sync.aligned.m16n8k8.row.col.f32.tf32.tf32.f32 "
        "{%0,%1,%2,%3}, {%4,%5,%6,%7}, {%8,%9}, {%0,%1,%2,%3};"
        : "+f"(d[0]), "+f"(d[1]), "+f"(d[2]), "+f"(d[3])
        : "r"(a[0]), "r"(a[1]), "r"(a[2]), "r"(a[3]), "r"(b[0]), "r"(b[1]));
}

// ---------------------------------------------------------------------------
// Pre-round pass: out[i] = tf32_rna(in[i])  (float4)
// ---------------------------------------------------------------------------
__global__ void __launch_bounds__(256) round4(const float4* __restrict__ in,
                                              float4* __restrict__ out, int n4) {
    int i = blockIdx.x * blockDim.x + threadIdx.x;
    if (i < n4) {
        float4 v = in[i];
        v.x = tf32r(v.x); v.y = tf32r(v.y); v.z = tf32r(v.z); v.w = tf32r(v.w);
        out[i] = v;
    }
}

// ---------------------------------------------------------------------------
// Expand Swin rel-pos bias table -> g_bias[h][row][col]
// ---------------------------------------------------------------------------
__global__ void __launch_bounds__(256) bias_expand(const float* __restrict__ btab,
                                                   float* __restrict__ gb) {
    int i = blockIdx.x * 256 + threadIdx.x;     // 0 .. 65535
    int h = i >> 12;
    int rc = i & 4095;
    int row = rc >> 6, col = rc & 63;
    int yi = row >> 3, xi = row & 7;
    int yj = col >> 3, xj = col & 7;
    int idx = (yi - yj + 7) * 15 + (xi - xj + 7);
    gb[i] = btab[idx * NH + h];
}

// ---------------------------------------------------------------------------
// GEMM (R3 config — best measured): C = A @ W^T + bias
// 128x128x32 tiles, 256 threads (8 warps 2x4), warp tile 64x32.
// cp.async 3-stage pipeline, 2 CTAs/SM.
// ---------------------------------------------------------------------------
#define BM 128
#define BN 128
#define BK 32
#define LDT 36
#define ROWB 144
#define STG_A (128 * ROWB)               // 18432 B
#define STG (2 * STG_A)                  // 36864 B per stage
#define STAGES 3
#define GSMEM (STAGES * STG)             // 110592 B

__global__ void __launch_bounds__(256, 2) gemm_hmma(
    const float* __restrict__ A, const float* __restrict__ W,
    const float* __restrict__ bias, float* __restrict__ C,
    int N, int K)
{
    extern __shared__ float smem[];
    const uint32_t sb = smem_u32(smem);
    const int tid  = threadIdx.x;
    const int lane = tid & 31;
    const int warp = tid >> 5;
    const int wm   = warp >> 2;
    const int wn   = warp & 3;
    const int mb   = blockIdx.y * BM;
    const int nb   = blockIdx.x * BN;

    const int jr = tid >> 3;
    const int cb = tid & 7;
    const float* Ag = A + (size_t)(mb + jr) * K + cb * 4;
    const float* Wg = W + (size_t)(nb + jr) * K + cb * 4;
    const uint32_t soff = (uint32_t)(jr * ROWB + cb * 16);

    #pragma unroll
    for (int s = 0; s < STAGES; s++) {
        const uint32_t b = sb + s * STG;
        #pragma unroll
        for (int p = 0; p < 4; p++)
            cp16(b + soff + p * 32 * ROWB, Ag + s * BK + (size_t)p * 32 * K);
        #pragma unroll
        for (int p = 0; p < 4; p++)
            cp16(b + STG_A + soff + p * 32 * ROWB, Wg + s * BK + (size_t)p * 32 * K);
        asm volatile("cp.async.commit_group;" ::: "memory");
    }

    float acc[4][4][4] = {};
    const int KT = K / BK;

    for (int kt = 0; kt < KT; kt++) {
        asm volatile("cp.async.wait_group %0;" :: "n"(STAGES - 1) : "memory");
        __syncthreads();
        const int buf = kt % STAGES;
        const float* Ab = smem + buf * (STG / 4) + (wm * 64) * LDT;
        const float* Bb = smem + buf * (STG / 4) + (STG_A / 4) + (wn * 32) * LDT;

        #pragma unroll
        for (int ks = 0; ks < 4; ks++) {
            const int k8 = ks * 8;
            uint32_t afr[4][4], bfr[4][2];
            #pragma unroll
            for (int mi = 0; mi < 4; mi++) {
                const float* p = Ab + (mi * 16 + (lane >> 2)) * LDT + k8 + (lane & 3);
                afr[mi][0] = __float_as_uint(p[0]);
                afr[mi][1] = __float_as_uint(p[8 * LDT]);
                afr[mi][2] = __float_as_uint(p[4]);
                afr[mi][3] = __float_as_uint(p[8 * LDT + 4]);
            }
            #pragma unroll
            for (int ni = 0; ni < 4; ni++) {
                const float* p = Bb + (ni * 8 + (lane >> 2)) * LDT + k8 + (lane & 3);
                bfr[ni][0] = __float_as_uint(p[0]);
                bfr[ni][1] = __float_as_uint(p[4]);
            }
            #pragma unroll
            for (int mi = 0; mi < 4; mi++)
                #pragma unroll
                for (int ni = 0; ni < 4; ni++)
                    mma_tf32(acc[mi][ni], afr[mi], bfr[ni]);
        }
        __syncthreads();

        const int nk = kt + STAGES;
        if (nk < KT) {
            const uint32_t b = sb + buf * STG;
            #pragma unroll
            for (int p = 0; p < 4; p++)
                cp16(b + soff + p * 32 * ROWB, Ag + nk * BK + (size_t)p * 32 * K);
            #pragma unroll
            for (int p = 0; p < 4; p++)
                cp16(b + STG_A + soff + p * 32 * ROWB, Wg + nk * BK + (size_t)p * 32 * K);
            asm volatile("cp.async.commit_group;" ::: "memory");
        }
    }

    #pragma unroll
    for (int mi = 0; mi < 4; mi++) {
        const int row = mb + wm * 64 + mi * 16 + (lane >> 2);
        #pragma unroll
        for (int ni = 0; ni < 4; ni++) {
            const int col = nb + wn * 32 + ni * 8 + (lane & 3) * 2;
            const float b0 = __ldg(bias + col), b1 = __ldg(bias + col + 1);
            float* Cp = C + (size_t)row * N + col;
            *(float2*)Cp = make_float2(acc[mi][ni][0] + b0, acc[mi][ni][1] + b1);
            *(float2*)(Cp + (size_t)8 * N) =
                make_float2(acc[mi][ni][2] + b0, acc[mi][ni][3] + b1);
        }
    }
}

// ---------------------------------------------------------------------------
// Attention v2: one (b,h) per block, 128 threads.
// Register softmax (quad shuffles), P aliased over Qs/Ks (27KB smem),
// precomputed bias (coalesced), output tf32-rounded.
// ---------------------------------------------------------------------------
__global__ void __launch_bounds__(128, 6) attn_kernel(
    const float* __restrict__ qkv, const float* __restrict__ gbias,
    float* __restrict__ out)
{
    __shared__ float sm[2 * 64 * 36];          // Qs | Ks, later aliased by P
    __shared__ float Vt[32][68];
    float (*Qs)[36] = (float(*)[36])sm;
    float (*Ks)[36] = (float(*)[36])(sm + 64 * 36);
    float (*P)[68]  = (float(*)[68])sm;        // alias (17408B <= 18432B)

    const int bh = blockIdx.x;
    const int b = bh >> 4;
    const int h = bh & 15;
    const int tid = threadIdx.x;
    const int lane = tid & 31;
    const int warp = tid >> 5;

    const float* base = qkv + (size_t)b * NTOK * QKVCOLS + h * HD;

    #pragma unroll
    for (int i = 0; i < 4; i++) {
        const int id = tid + i * 128;
        const int n = id >> 3;
        const int c4 = (id & 7) * 4;
        float4 q = *(const float4*)(base + (size_t)n * QKVCOLS + c4);
        q.x = tf32r(q.x * SCALE); q.y = tf32r(q.y * SCALE);
        q.z = tf32r(q.z * SCALE); q.w = tf32r(q.w * SCALE);
        *(float4*)(&Qs[n][c4]) = q;
        float4 k = *(const float4*)(base + (size_t)n * QKVCOLS + DIM + c4);
        k.x = tf32r(k.x); k.y = tf32r(k.y); k.z = tf32r(k.z); k.w = tf32r(k.w);
        *(float4*)(&Ks[n][c4]) = k;
    }
    for (int i = tid; i < NTOK * HD; i += 128) {
        const int m = i >> 5, d = i & 31;
        Vt[d][m] = tf32r(base[(size_t)m * QKVCOLS + 2 * DIM + d]);
    }
    __syncthreads();

    // --- S = Qs @ Ks^T ---
    float sacc[8][4] = {};
    #pragma unroll
    for (int ks = 0; ks < 4; ks++) {
        const int k8 = ks * 8;
        uint32_t af[4];
        const float* p = &Qs[warp * 16 + (lane >> 2)][k8 + (lane & 3)];
        af[0] = __float_as_uint(p[0]);
        af[1] = __float_as_uint(p[8 * 36]);
        af[2] = __float_as_uint(p[4]);
        af[3] = __float_as_uint(p[8 * 36 + 4]);
        #pragma unroll
        for (int ni = 0; ni < 8; ni++) {
            uint32_t bf[2];
            const float* q = &Ks[ni * 8 + (lane >> 2)][k8 + (lane & 3)];
            bf[0] = __float_as_uint(q[0]);
            bf[1] = __float_as_uint(q[4]);
            mma_tf32(sacc[ni], af, bf);
        }
    }

    // --- bias (coalesced) + register softmax via quad shuffles ---
    const int rA = warp * 16 + (lane >> 2);
    const int c0 = (lane & 3) * 2;
    {
        const float* gb = gbias + h * (NTOK * NTOK);
        #pragma unroll
        for (int ni = 0; ni < 8; ni++) {
            const int col = ni * 8 + c0;
            float2 b0 = *(const float2*)(gb + rA * 64 + col);
            float2 b1 = *(const float2*)(gb + (rA + 8) * 64 + col);
            sacc[ni][0] += b0.x; sacc[ni][1] += b0.y;
            sacc[ni][2] += b1.x; sacc[ni][3] += b1.y;
        }
    }
    float mx0 = -1e30f, mx1 = -1e30f;
    #pragma unroll
    for (int ni = 0; ni < 8; ni++) {
        mx0 = fmaxf(mx0, fmaxf(sacc[ni][0], sacc[ni][1]));
        mx1 = fmaxf(mx1, fmaxf(sacc[ni][2], sacc[ni][3]));
    }
    mx0 = fmaxf(mx0, __shfl_xor_sync(0xffffffffu, mx0, 1));
    mx0 = fmaxf(mx0, __shfl_xor_sync(0xffffffffu, mx0, 2));
    mx1 = fmaxf(mx1, __shfl_xor_sync(0xffffffffu, mx1, 1));
    mx1 = fmaxf(mx1, __shfl_xor_sync(0xffffffffu, mx1, 2));

    float sum0 = 0.f, sum1 = 0.f;
    #pragma unroll
    for (int ni = 0; ni < 8; ni++) {
        sacc[ni][0] = __expf(sacc[ni][0] - mx0);
        sacc[ni][1] = __expf(sacc[ni][1] - mx0);
        sacc[ni][2] = __expf(sacc[ni][2] - mx1);
        sacc[ni][3] = __expf(sacc[ni][3] - mx1);
        sum0 += sacc[ni][0] + sacc[ni][1];
        sum1 += sacc[ni][2] + sacc[ni][3];
    }
    sum0 += __shfl_xor_sync(0xffffffffu, sum0, 1);
    sum0 += __shfl_xor_sync(0xffffffffu, sum0, 2);
    sum1 += __shfl_xor_sync(0xffffffffu, sum1, 1);
    sum1 += __shfl_xor_sync(0xffffffffu, sum1, 2);
    const float inv0 = 1.f / sum0, inv1 = 1.f / sum1;

    __syncthreads();   // all Qs/Ks readers done before P overwrites them

    #pragma unroll
    for (int ni = 0; ni < 8; ni++) {
        const int col = ni * 8 + c0;
        *(float2*)(&P[rA][col]) =
            make_float2(tf32r(sacc[ni][0] * inv0), tf32r(sacc[ni][1] * inv0));
        *(float2*)(&P[rA + 8][col]) =
            make_float2(tf32r(sacc[ni][2] * inv1), tf32r(sacc[ni][3] * inv1));
    }
    __syncthreads();

    // --- O = P @ V ---
    float oacc[4][4] = {};
    #pragma unroll
    for (int ks = 0; ks < 8; ks++) {
        const int k8 = ks * 8;
        uint32_t af[4];
        const float* p = &P[warp * 16 + (lane >> 2)][k8 + (lane & 3)];
        af[0] = __float_as_uint(p[0]);
        af[1] = __float_as_uint(p[8 * 68]);
        af[2] = __float_as_uint(p[4]);
        af[3] = __float_as_uint(p[8 * 68 + 4]);
        #pragma unroll
        for (int ni = 0; ni < 4; ni++) {
            uint32_t bf[2];
            const float* q = &Vt[ni * 8 + (lane >> 2)][k8 + (lane & 3)];
            bf[0] = __float_as_uint(q[0]);
            bf[1] = __float_as_uint(q[4]);
            mma_tf32(oacc[ni], af, bf);
        }
    }
    {
        float* ob = out + (size_t)b * NTOK * DIM + h * HD;
        #pragma unroll
        for (int ni = 0; ni < 4; ni++) {
            const int col = ni * 8 + c0;
            *(float2*)(ob + (size_t)rA * DIM + col) =
                make_float2(tf32r(oacc[ni][0]), tf32r(oacc[ni][1]));
            *(float2*)(ob + (size_t)(rA + 8) * DIM + col) =
                make_float2(tf32r(oacc[ni][2]), tf32r(oacc[ni][3]));
        }
    }
}

// ---------------------------------------------------------------------------
extern "C" void kernel_launch(void* const* d_in, const int* in_sizes, int n_in,
                              void* d_out, int out_size)
{
    const float* x     = (const float*)d_in[0];
    const float* Wqkv  = (const float*)d_in[1];
    const float* bqkv  = (const float*)d_in[2];
    const float* Wproj = (const float*)d_in[3];
    const float* bproj = (const float*)d_in[4];
    const float* btab  = (const float*)d_in[5];
    float* out = (float*)d_out;

    float *qkvbuf, *attnbuf, *xr, *wqkvr, *wprojr, *gbias;
    cudaGetSymbolAddress((void**)&qkvbuf, g_qkv);
    cudaGetSymbolAddress((void**)&attnbuf, g_attn);
    cudaGetSymbolAddress((void**)&xr, g_xr);
    cudaGetSymbolAddress((void**)&wqkvr, g_wqkv);
    cudaGetSymbolAddress((void**)&wprojr, g_wproj);
    cudaGetSymbolAddress((void**)&gbias, g_bias);

    cudaFuncSetAttribute(gemm_hmma, cudaFuncAttributeMaxDynamicSharedMemorySize, GSMEM);

    // 0) tf32-round inputs; expand bias table
    {
        int n4 = MROWS * DIM / 4;
        round4<<<(n4 + 255) / 256, 256>>>((const float4*)x, (float4*)xr, n4);
        n4 = QKVCOLS * DIM / 4;
        round4<<<(n4 + 255) / 256, 256>>>((const float4*)Wqkv, (float4*)wqkvr, n4);
        n4 = DIM * DIM / 4;
        round4<<<(n4 + 255) / 256, 256>>>((const float4*)Wproj, (float4*)wprojr, n4);
        bias_expand<<<NH * NTOK * NTOK / 256, 256>>>(btab, gbias);
    }

    // 1) QKV projection
    gemm_hmma<<<dim3(QKVCOLS / BN, MROWS / BM), 256, GSMEM>>>(
        xr, wqkvr, bqkv, qkvbuf, QKVCOLS, DIM);

    // 2) Windowed attention per (b, h)
    attn_kernel<<<BATCH * NH, 128>>>(qkvbuf, gbias, attnbuf);

    // 3) Output projection
    gemm_hmma<<<dim3(DIM / BN, MROWS / BM), 256, GSMEM>>>(
        attnbuf, wprojr, bproj, out, DIM, DIM);
}

// round 8
// speedup vs baseline: 1.2362x; 1.1154x over previous
#include <cuda_runtime.h>
#include <cstdint>

// Problem constants
#define BATCH   2048
#define NTOK    64
#define DIM     512
#define NH      16
#define HD      32
#define MROWS   (BATCH * NTOK)      // 131072
#define QKVCOLS (3 * DIM)           // 1536
#define SCALE   0.17677669529663687f // 32^-0.5

// Scratch (allocation-free: __device__ globals)
__device__ float g_qkv[(size_t)MROWS * QKVCOLS];   // [B*N, 1536] (rounded, Q pre-scaled)
__device__ float g_attn[(size_t)MROWS * DIM];      // [B*N, 512] (tf32-rounded)
__device__ float g_xr[(size_t)MROWS * DIM];        // tf32-rounded x
__device__ float g_wqkv[(size_t)QKVCOLS * DIM];    // tf32-rounded W_qkv
__device__ float g_wproj[(size_t)DIM * DIM];       // tf32-rounded W_proj
__device__ float g_bias[NH * NTOK * NTOK];         // expanded rel-pos bias

__device__ __forceinline__ float tf32r(float x) {
    float y;
    asm("cvt.rna.tf32.f32 %0, %1;" : "=f"(y) : "f"(x));
    return y;
}

__device__ __forceinline__ uint32_t smem_u32(const void* p) {
    uint32_t a;
    asm("{ .reg .u64 t; cvta.to.shared.u64 t, %1; cvt.u32.u64 %0, t; }" : "=r"(a) : "l"(p));
    return a;
}

__device__ __forceinline__ void cp16(uint32_t s, const void* g) {
    asm volatile("cp.async.cg.shared.global [%0], [%1], 16;" :: "r"(s), "l"(g));
}

__device__ __forceinline__ void mma_tf32(float* d, const uint32_t* a, const uint32_t* b) {
    asm volatile(
        "mma.sync.aligned.m16n8k8.row.col.f32.tf32.tf32.f32 "
        "{%0,%1,%2,%3}, {%4,%5,%6,%7}, {%8,%9}, {%0,%1,%2,%3};"
        : "+f"(d[0]), "+f"(d[1]), "+f"(d[2]), "+f"(d[3])
        : "r"(a[0]), "r"(a[1]), "r"(a[2]), "r"(a[3]), "r"(b[0]), "r"(b[1]));
}

// ---------------------------------------------------------------------------
// Pre-round pass: out[i] = tf32_rna(in[i])  (float4)
// ---------------------------------------------------------------------------
__global__ void __launch_bounds__(256) round4(const float4* __restrict__ in,
                                              float4* __restrict__ out, int n4) {
    int i = blockIdx.x * blockDim.x + threadIdx.x;
    if (i < n4) {
        float4 v = in[i];
        v.x = tf32r(v.x); v.y = tf32r(v.y); v.z = tf32r(v.z); v.w = tf32r(v.w);
        out[i] = v;
    }
}

// ---------------------------------------------------------------------------
// Expand Swin rel-pos bias table -> g_bias[h][row][col]
// ---------------------------------------------------------------------------
__global__ void __launch_bounds__(256) bias_expand(const float* __restrict__ btab,
                                                   float* __restrict__ gb) {
    int i = blockIdx.x * 256 + threadIdx.x;
    int h = i >> 12;
    int rc = i & 4095;
    int row = rc >> 6, col = rc & 63;
    int yi = row >> 3, xi = row & 7;
    int yj = col >> 3, xj = col & 7;
    int idx = (yi - yj + 7) * 15 + (xi - xj + 7);
    gb[i] = btab[idx * NH + h];
}

// ---------------------------------------------------------------------------
// GEMM (R3 config): C = A @ W^T + bias.  MODE 0: plain fp32 store (proj).
// MODE 1: qkv epilogue — tf32-round everything, pre-scale Q cols (<DIM).
// 128x128x32, 256 thr (8 warps 2x4), warp tile 64x32, 3-stage cp.async, 2 CTA/SM.
// ---------------------------------------------------------------------------
#define BM 128
#define BN 128
#define BK 32
#define LDT 36
#define ROWB 144
#define STG_A (128 * ROWB)               // 18432 B
#define STG (2 * STG_A)                  // 36864 B per stage
#define STAGES 3
#define GSMEM (STAGES * STG)             // 110592 B

template<int MODE>
__global__ void __launch_bounds__(256, 2) gemm_hmma(
    const float* __restrict__ A, const float* __restrict__ W,
    const float* __restrict__ bias, float* __restrict__ C,
    int N, int K)
{
    extern __shared__ float smem[];
    const uint32_t sb = smem_u32(smem);
    const int tid  = threadIdx.x;
    const int lane = tid & 31;
    const int warp = tid >> 5;
    const int wm   = warp >> 2;
    const int wn   = warp & 3;
    const int mb   = blockIdx.y * BM;
    const int nb   = blockIdx.x * BN;

    const int jr = tid >> 3;
    const int cb = tid & 7;
    const float* Ag = A + (size_t)(mb + jr) * K + cb * 4;
    const float* Wg = W + (size_t)(nb + jr) * K + cb * 4;
    const uint32_t soff = (uint32_t)(jr * ROWB + cb * 16);

    #pragma unroll
    for (int s = 0; s < STAGES; s++) {
        const uint32_t b = sb + s * STG;
        #pragma unroll
        for (int p = 0; p < 4; p++)
            cp16(b + soff + p * 32 * ROWB, Ag + s * BK + (size_t)p * 32 * K);
        #pragma unroll
        for (int p = 0; p < 4; p++)
            cp16(b + STG_A + soff + p * 32 * ROWB, Wg + s * BK + (size_t)p * 32 * K);
        asm volatile("cp.async.commit_group;" ::: "memory");
    }

    float acc[4][4][4] = {};
    const int KT = K / BK;

    for (int kt = 0; kt < KT; kt++) {
        asm volatile("cp.async.wait_group %0;" :: "n"(STAGES - 1) : "memory");
        __syncthreads();
        const int buf = kt % STAGES;
        const float* Ab = smem + buf * (STG / 4) + (wm * 64) * LDT;
        const float* Bb = smem + buf * (STG / 4) + (STG_A / 4) + (wn * 32) * LDT;

        #pragma unroll
        for (int ks = 0; ks < 4; ks++) {
            const int k8 = ks * 8;
            uint32_t afr[4][4], bfr[4][2];
            #pragma unroll
            for (int mi = 0; mi < 4; mi++) {
                const float* p = Ab + (mi * 16 + (lane >> 2)) * LDT + k8 + (lane & 3);
                afr[mi][0] = __float_as_uint(p[0]);
                afr[mi][1] = __float_as_uint(p[8 * LDT]);
                afr[mi][2] = __float_as_uint(p[4]);
                afr[mi][3] = __float_as_uint(p[8 * LDT + 4]);
            }
            #pragma unroll
            for (int ni = 0; ni < 4; ni++) {
                const float* p = Bb + (ni * 8 + (lane >> 2)) * LDT + k8 + (lane & 3);
                bfr[ni][0] = __float_as_uint(p[0]);
                bfr[ni][1] = __float_as_uint(p[4]);
            }
            #pragma unroll
            for (int mi = 0; mi < 4; mi++)
                #pragma unroll
                for (int ni = 0; ni < 4; ni++)
                    mma_tf32(acc[mi][ni], afr[mi], bfr[ni]);
        }
        __syncthreads();

        const int nk = kt + STAGES;
        if (nk < KT) {
            const uint32_t b = sb + buf * STG;
            #pragma unroll
            for (int p = 0; p < 4; p++)
                cp16(b + soff + p * 32 * ROWB, Ag + nk * BK + (size_t)p * 32 * K);
            #pragma unroll
            for (int p = 0; p < 4; p++)
                cp16(b + STG_A + soff + p * 32 * ROWB, Wg + nk * BK + (size_t)p * 32 * K);
            asm volatile("cp.async.commit_group;" ::: "memory");
        }
    }

    #pragma unroll
    for (int mi = 0; mi < 4; mi++) {
        const int row = mb + wm * 64 + mi * 16 + (lane >> 2);
        #pragma unroll
        for (int ni = 0; ni < 4; ni++) {
            const int col = nb + wn * 32 + ni * 8 + (lane & 3) * 2;
            const float b0 = __ldg(bias + col), b1 = __ldg(bias + col + 1);
            float* Cp = C + (size_t)row * N + col;
            float v0 = acc[mi][ni][0] + b0, v1 = acc[mi][ni][1] + b1;
            float v2 = acc[mi][ni][2] + b0, v3 = acc[mi][ni][3] + b1;
            if (MODE == 1) {
                const float s = (col < DIM) ? SCALE : 1.0f;   // Q pre-scale
                v0 = tf32r(v0 * s); v1 = tf32r(v1 * s);
                v2 = tf32r(v2 * s); v3 = tf32r(v3 * s);
            }
            *(float2*)Cp = make_float2(v0, v1);
            *(float2*)(Cp + (size_t)8 * N) = make_float2(v2, v3);
        }
    }
}

// ---------------------------------------------------------------------------
// Attention v3: one (b,h) per block, 128 threads.
// Pure cp.async loads (qkv already rounded/scaled by GEMM1 epilogue).
// V kept [m][40] (conflict-free PV B-frags, no transpose).
// Register softmax; P aliases Qs/Ks.
// ---------------------------------------------------------------------------
#define QK_ROWB 144                       // 36 floats
#define V_ROWB  160                       // 40 floats

__global__ void __launch_bounds__(128, 6) attn_kernel(
    const float* __restrict__ qkv, const float* __restrict__ gbias,
    float* __restrict__ out)
{
    __shared__ float sm[2 * 64 * 36];          // Qs | Ks; later aliased by P
    __shared__ float Vs[64][40];
    float (*Qs)[36] = (float(*)[36])sm;
    float (*Ks)[36] = (float(*)[36])(sm + 64 * 36);
    float (*P)[68]  = (float(*)[68])sm;        // alias 17408B <= 18432B

    const int bh = blockIdx.x;
    const int b = bh >> 4;
    const int h = bh & 15;
    const int tid = threadIdx.x;
    const int lane = tid & 31;
    const int warp = tid >> 5;

    const float* base = qkv + (size_t)b * NTOK * QKVCOLS + h * HD;
    const uint32_t sq = smem_u32(sm);
    const uint32_t sv = smem_u32(Vs);

    // 12 cp.async per thread: Q, K, V (each 64 rows x 8 16B-chunks)
    #pragma unroll
    for (int p = 0; p < 4; p++) {
        const int t = tid + p * 128;           // 0..511
        const int row = t >> 3, c = t & 7;
        const float* g = base + (size_t)row * QKVCOLS + c * 4;
        cp16(sq + row * QK_ROWB + c * 16, g);                        // Q
        cp16(sq + 64 * QK_ROWB + row * QK_ROWB + c * 16, g + DIM);   // K
        cp16(sv + row * V_ROWB + c * 16, g + 2 * DIM);               // V
    }
    asm volatile("cp.async.commit_group;" ::: "memory");
    asm volatile("cp.async.wait_group 0;" ::: "memory");
    __syncthreads();

    // --- S = Qs @ Ks^T  (Q pre-scaled) ---
    float sacc[8][4] = {};
    #pragma unroll
    for (int ks = 0; ks < 4; ks++) {
        const int k8 = ks * 8;
        uint32_t af[4];
        const float* p = &Qs[warp * 16 + (lane >> 2)][k8 + (lane & 3)];
        af[0] = __float_as_uint(p[0]);
        af[1] = __float_as_uint(p[8 * 36]);
        af[2] = __float_as_uint(p[4]);
        af[3] = __float_as_uint(p[8 * 36 + 4]);
        #pragma unroll
        for (int ni = 0; ni < 8; ni++) {
            uint32_t bf[2];
            const float* q = &Ks[ni * 8 + (lane >> 2)][k8 + (lane & 3)];
            bf[0] = __float_as_uint(q[0]);
            bf[1] = __float_as_uint(q[4]);
            mma_tf32(sacc[ni], af, bf);
        }
    }

    // --- bias + register softmax (quad shuffles) ---
    const int rA = warp * 16 + (lane >> 2);
    const int c0 = (lane & 3) * 2;
    {
        const float* gb = gbias + h * (NTOK * NTOK);
        #pragma unroll
        for (int ni = 0; ni < 8; ni++) {
            const int col = ni * 8 + c0;
            float2 b0 = *(const float2*)(gb + rA * 64 + col);
            float2 b1 = *(const float2*)(gb + (rA + 8) * 64 + col);
            sacc[ni][0] += b0.x; sacc[ni][1] += b0.y;
            sacc[ni][2] += b1.x; sacc[ni][3] += b1.y;
        }
    }
    float mx0 = -1e30f, mx1 = -1e30f;
    #pragma unroll
    for (int ni = 0; ni < 8; ni++) {
        mx0 = fmaxf(mx0, fmaxf(sacc[ni][0], sacc[ni][1]));
        mx1 = fmaxf(mx1, fmaxf(sacc[ni][2], sacc[ni][3]));
    }
    mx0 = fmaxf(mx0, __shfl_xor_sync(0xffffffffu, mx0, 1));
    mx0 = fmaxf(mx0, __shfl_xor_sync(0xffffffffu, mx0, 2));
    mx1 = fmaxf(mx1, __shfl_xor_sync(0xffffffffu, mx1, 1));
    mx1 = fmaxf(mx1, __shfl_xor_sync(0xffffffffu, mx1, 2));

    float sum0 = 0.f, sum1 = 0.f;
    #pragma unroll
    for (int ni = 0; ni < 8; ni++) {
        sacc[ni][0] = __expf(sacc[ni][0] - mx0);
        sacc[ni][1] = __expf(sacc[ni][1] - mx0);
        sacc[ni][2] = __expf(sacc[ni][2] - mx1);
        sacc[ni][3] = __expf(sacc[ni][3] - mx1);
        sum0 += sacc[ni][0] + sacc[ni][1];
        sum1 += sacc[ni][2] + sacc[ni][3];
    }
    sum0 += __shfl_xor_sync(0xffffffffu, sum0, 1);
    sum0 += __shfl_xor_sync(0xffffffffu, sum0, 2);
    sum1 += __shfl_xor_sync(0xffffffffu, sum1, 1);
    sum1 += __shfl_xor_sync(0xffffffffu, sum1, 2);
    const float inv0 = 1.f / sum0, inv1 = 1.f / sum1;

    __syncthreads();   // all Qs/Ks readers done before P overwrites

    #pragma unroll
    for (int ni = 0; ni < 8; ni++) {
        const int col = ni * 8 + c0;
        *(float2*)(&P[rA][col]) =
            make_float2(tf32r(sacc[ni][0] * inv0), tf32r(sacc[ni][1] * inv0));
        *(float2*)(&P[rA + 8][col]) =
            make_float2(tf32r(sacc[ni][2] * inv1), tf32r(sacc[ni][3] * inv1));
    }
    __syncthreads();

    // --- O = P @ V : B-frags straight from Vs[m][40] (conflict-free) ---
    float oacc[4][4] = {};
    #pragma unroll
    for (int ks = 0; ks < 8; ks++) {
        const int k8 = ks * 8;
        uint32_t af[4];
        const float* p = &P[warp * 16 + (lane >> 2)][k8 + (lane & 3)];
        af[0] = __float_as_uint(p[0]);
        af[1] = __float_as_uint(p[8 * 68]);
        af[2] = __float_as_uint(p[4]);
        af[3] = __float_as_uint(p[8 * 68 + 4]);
        #pragma unroll
        for (int ni = 0; ni < 4; ni++) {
            uint32_t bf[2];
            const float* q = &Vs[k8 + (lane & 3)][ni * 8 + (lane >> 2)];
            bf[0] = __float_as_uint(q[0]);
            bf[1] = __float_as_uint(q[4 * 40]);
            mma_tf32(oacc[ni], af, bf);
        }
    }
    {
        float* ob = out + (size_t)b * NTOK * DIM + h * HD;
        #pragma unroll
        for (int ni = 0; ni < 4; ni++) {
            const int col = ni * 8 + c0;
            *(float2*)(ob + (size_t)rA * DIM + col) =
                make_float2(tf32r(oacc[ni][0]), tf32r(oacc[ni][1]));
            *(float2*)(ob + (size_t)(rA + 8) * DIM + col) =
                make_float2(tf32r(oacc[ni][2]), tf32r(oacc[ni][3]));
        }
    }
}

// ---------------------------------------------------------------------------
extern "C" void kernel_launch(void* const* d_in, const int* in_sizes, int n_in,
                              void* d_out, int out_size)
{
    const float* x     = (const float*)d_in[0];
    const float* Wqkv  = (const float*)d_in[1];
    const float* bqkv  = (const float*)d_in[2];
    const float* Wproj = (const float*)d_in[3];
    const float* bproj = (const float*)d_in[4];
    const float* btab  = (const float*)d_in[5];
    float* out = (float*)d_out;

    float *qkvbuf, *attnbuf, *xr, *wqkvr, *wprojr, *gbias;
    cudaGetSymbolAddress((void**)&qkvbuf, g_qkv);
    cudaGetSymbolAddress((void**)&attnbuf, g_attn);
    cudaGetSymbolAddress((void**)&xr, g_xr);
    cudaGetSymbolAddress((void**)&wqkvr, g_wqkv);
    cudaGetSymbolAddress((void**)&wprojr, g_wproj);
    cudaGetSymbolAddress((void**)&gbias, g_bias);

    cudaFuncSetAttribute(gemm_hmma<0>, cudaFuncAttributeMaxDynamicSharedMemorySize, GSMEM);
    cudaFuncSetAttribute(gemm_hmma<1>, cudaFuncAttributeMaxDynamicSharedMemorySize, GSMEM);

    // 0) tf32-round inputs; expand bias table
    {
        int n4 = MROWS * DIM / 4;
        round4<<<(n4 + 255) / 256, 256>>>((const float4*)x, (float4*)xr, n4);
        n4 = QKVCOLS * DIM / 4;
        round4<<<(n4 + 255) / 256, 256>>>((const float4*)Wqkv, (float4*)wqkvr, n4);
        n4 = DIM * DIM / 4;
        round4<<<(n4 + 255) / 256, 256>>>((const float4*)Wproj, (float4*)wprojr, n4);
        bias_expand<<<NH * NTOK * NTOK / 256, 256>>>(btab, gbias);
    }

    // 1) QKV projection (epilogue rounds + pre-scales Q)
    gemm_hmma<1><<<dim3(QKVCOLS / BN, MROWS / BM), 256, GSMEM>>>(
        xr, wqkvr, bqkv, qkvbuf, QKVCOLS, DIM);

    // 2) Windowed attention per (b, h)
    attn_kernel<<<BATCH * NH, 128>>>(qkvbuf, gbias, attnbuf);

    // 3) Output projection
    gemm_hmma<0><<<dim3(DIM / BN, MROWS / BM), 256, GSMEM>>>(
        attnbuf, wprojr, bproj, out, DIM, DIM);
}